// round 5
// baseline (speedup 1.0000x reference)
#include <cuda_runtime.h>
#include <cstdint>

// Shapes (fixed by problem):
// x:(16384,4096) f32, latency:(16384) f32, W:(4096,1536) f32, b:(1536) f32,
// u:(16384,24,32,2) f32  -> out:(16384,32,2,32) f32
#define NB      16384
#define HID     4096
#define NCOLS   768        // head-diff columns (24*32)
#define NGROUPS 384
#define TAU_INV 0.2f

__device__ float g_dW[HID * NCOLS];           // 12.6 MB scratch
__device__ float g_scores[NB * NGROUPS];      // 25.2 MB scratch

// ---------------------------------------------------------------------------
// Kernel A: dW[k][n] = W[k][2n] - W[k][2n+1]
// ---------------------------------------------------------------------------
__global__ void prep_dw_kernel(const float* __restrict__ W) {
    int idx = blockIdx.x * blockDim.x + threadIdx.x;
    if (idx < HID * NCOLS) {
        int k = idx / NCOLS;
        int n = idx - k * NCOLS;
        const float* wr = W + (size_t)k * (2 * NCOLS) + 2 * n;
        g_dW[idx] = wr[0] - wr[1];
    }
}

// ---------------------------------------------------------------------------
// Kernel B: 128x128x8 tiled fp32 GEMM (packed f32x2 FMA) + fused
// gumbel/sigmoid/score epilogue.
// ---------------------------------------------------------------------------
#define BM 128
#define BN 128
#define BK 8

__device__ __forceinline__ unsigned long long pack2(float lo, float hi) {
    unsigned long long r;
    asm("mov.b64 %0, {%1, %2};" : "=l"(r) : "f"(lo), "f"(hi));
    return r;
}
__device__ __forceinline__ void fma2(unsigned long long& d,
                                     unsigned long long a, unsigned long long b) {
    asm("fma.rn.f32x2 %0, %1, %2, %0;" : "+l"(d) : "l"(a), "l"(b));
}
__device__ __forceinline__ float2 unpack2(unsigned long long v) {
    float2 r;
    asm("mov.b64 {%0, %1}, %2;" : "=f"(r.x), "=f"(r.y) : "l"(v));
    return r;
}
__device__ __forceinline__ float gumbel(float v) {
    float t = v * (1.0f - 2e-6f) + 1e-6f;
    return -logf(-logf(t));
}

__global__ __launch_bounds__(256, 2)
void gemm_score_kernel(const float* __restrict__ x,
                       const float* __restrict__ bias,
                       const float* __restrict__ u) {
    __shared__ float As[2][BK][BM + 4];
    __shared__ float Bs[2][BK][BN];

    const int tid = threadIdx.x;
    const int bi  = blockIdx.x;
    const int bm  = (bi / (NCOLS / BN)) * BM;
    const int bn  = (bi % (NCOLS / BN)) * BN;

    const int tx  = tid & 15;
    const int ty  = tid >> 4;
    const int tx4 = tx * 4;
    const int ty4 = ty * 4;

    // global-load assignments
    const int arow  = tid >> 1;          // 0..127
    const int akoff = (tid & 1) * 4;     // 0 or 4
    const int brow  = tid >> 5;          // 0..7
    const int bcol  = (tid & 31) * 4;    // 0..124

    const float* gA = x + (size_t)(bm + arow) * HID + akoff;
    const float* gB = g_dW + (size_t)brow * NCOLS + bn + bcol;

    unsigned long long acc[8][4];
#pragma unroll
    for (int i = 0; i < 8; i++)
#pragma unroll
        for (int j = 0; j < 4; j++) acc[i][j] = 0ull;

    // preload tile 0
    float4 fa = *(const float4*)(gA);
    float4 fb = *(const float4*)(gB);
    As[0][akoff + 0][arow] = fa.x;
    As[0][akoff + 1][arow] = fa.y;
    As[0][akoff + 2][arow] = fa.z;
    As[0][akoff + 3][arow] = fa.w;
    *(float4*)&Bs[0][brow][bcol] = fb;
    __syncthreads();

    const int KT = HID / BK;  // 512
    int cur = 0;
    for (int t = 0; t < KT; ++t) {
        if (t + 1 < KT) {
            fa = *(const float4*)(gA + (t + 1) * BK);
            fb = *(const float4*)(gB + (size_t)(t + 1) * BK * NCOLS);
        }
#pragma unroll
        for (int k = 0; k < BK; k++) {
            float4 a0 = *(const float4*)&As[cur][k][ty4];
            float4 a1 = *(const float4*)&As[cur][k][ty4 + 64];
            ulonglong2 b0 = *(const ulonglong2*)&Bs[cur][k][tx4];
            ulonglong2 b1 = *(const ulonglong2*)&Bs[cur][k][tx4 + 64];
            float av[8] = {a0.x, a0.y, a0.z, a0.w, a1.x, a1.y, a1.z, a1.w};
#pragma unroll
            for (int i = 0; i < 8; i++) {
                unsigned long long ap = pack2(av[i], av[i]);
                fma2(acc[i][0], ap, b0.x);
                fma2(acc[i][1], ap, b0.y);
                fma2(acc[i][2], ap, b1.x);
                fma2(acc[i][3], ap, b1.y);
            }
        }
        int nxt = cur ^ 1;
        if (t + 1 < KT) {
            As[nxt][akoff + 0][arow] = fa.x;
            As[nxt][akoff + 1][arow] = fa.y;
            As[nxt][akoff + 2][arow] = fa.z;
            As[nxt][akoff + 3][arow] = fa.w;
            *(float4*)&Bs[nxt][brow][bcol] = fb;
        }
        __syncthreads();
        cur = nxt;
    }

    // ---- epilogue: per owned head n -> p_keep, pair-mean -> group score ----
    // owned head cols: n = bn+tx4 + {0..3}  and  bn+tx4+64 + {0..3}
    float db[8];
#pragma unroll
    for (int j = 0; j < 8; j++) {
        int n = bn + tx4 + ((j >> 2) * 64) + (j & 3);
        db[j] = bias[2 * n] - bias[2 * n + 1];
    }
    const int gbase = (bn >> 1) + tx4 / 2;   // group base for first segment

#pragma unroll
    for (int i = 0; i < 8; i++) {
        int m = bm + ty4 + (i & 3) + ((i >> 2) * 64);
        const float* up = u + (size_t)m * (2 * NCOLS);
        int off0 = 2 * (bn + tx4);
        int off1 = 2 * (bn + tx4 + 64);
        float4 ua0 = *(const float4*)(up + off0);
        float4 ua1 = *(const float4*)(up + off0 + 4);
        float4 ub0 = *(const float4*)(up + off1);
        float4 ub1 = *(const float4*)(up + off1 + 4);
        float uv[16] = {ua0.x, ua0.y, ua0.z, ua0.w, ua1.x, ua1.y, ua1.z, ua1.w,
                        ub0.x, ub0.y, ub0.z, ub0.w, ub1.x, ub1.y, ub1.z, ub1.w};
        float2 d0 = unpack2(acc[i][0]);
        float2 d1 = unpack2(acc[i][1]);
        float2 d2 = unpack2(acc[i][2]);
        float2 d3 = unpack2(acc[i][3]);
        float dl[8] = {d0.x, d0.y, d1.x, d1.y, d2.x, d2.y, d3.x, d3.y};

        float p[8];
#pragma unroll
        for (int h = 0; h < 8; h++) {
            float g0 = gumbel(uv[2 * h]);
            float g1 = gumbel(uv[2 * h + 1]);
            float z  = (dl[h] + db[h] + g0 - g1) * TAU_INV;
            p[h] = 1.0f / (1.0f + __expf(-z));
        }
        float* sc = g_scores + (size_t)m * NGROUPS;
        sc[gbase + 0]  = 0.5f * (p[0] + p[1]);
        sc[gbase + 1]  = 0.5f * (p[2] + p[3]);
        sc[gbase + 32] = 0.5f * (p[4] + p[5]);
        sc[gbase + 33] = 0.5f * (p[6] + p[7]);
    }
}

// ---------------------------------------------------------------------------
// Kernel C: per-sample top-budget selection (bitwise binary search on float
// bits via __syncthreads_count) + hard-mask output write.
// ---------------------------------------------------------------------------
__global__ __launch_bounds__(NGROUPS)
void rank_out_kernel(const float* __restrict__ latency, float* __restrict__ out) {
    __shared__ float kf[NGROUPS];
    __shared__ int   wsum[NGROUPS / 32];

    const int b = blockIdx.x;
    const int t = threadIdx.x;

    // budget: clip(round(latency*512), 128, 512) - 128  (round-half-even)
    float units = rintf(latency[b] * 512.0f);
    units = fminf(fmaxf(units, 128.0f), 512.0f);
    const int budget = (int)units - 128;            // in [0, 384]

    // my score -> order-preserving uint key (scores are in (0,1))
    const unsigned key = __float_as_uint(g_scores[(size_t)b * NGROUPS + t]);

    // find T = largest value with count(key >= T) >= budget
    unsigned T = 0u;
#pragma unroll
    for (int bit = 31; bit >= 0; --bit) {
        unsigned cand = T | (1u << bit);
        int c = __syncthreads_count(key >= cand);
        if (c >= budget) T = cand;
    }
    const int cgt  = __syncthreads_count(key > T);
    const int need = budget - cgt;                  // # of ties to keep (by index)

    const bool eq = (key == T);
    unsigned ball = __ballot_sync(0xFFFFFFFFu, eq);
    const int lane = t & 31, w = t >> 5;
    if (lane == 0) wsum[w] = __popc(ball);
    __syncthreads();
    int pre = 0;
    for (int ww = 0; ww < w; ww++) pre += wsum[ww];
    const int rank_eq = pre + __popc(ball & ((1u << lane) - 1u));

    const bool keep = (key > T) || (eq && rank_eq < need);
    kf[t] = keep ? 1.0f : 0.0f;
    __syncthreads();

    // output (B, 32, 2, 32): layers 0..7 all ones; layer l>=8:
    //   [l][0][h] = keep(group), [l][1][h] = 1-keep(group), group=(l-8)*16+h/2
    float* ob = out + (size_t)b * 2048;
    for (int idx = t; idx < 2048; idx += NGROUPS) {
        int l = idx >> 6;
        int h = idx & 31;
        int r = (idx >> 5) & 1;
        float v;
        if (l < 8) {
            v = 1.0f;
        } else {
            float k = kf[(l - 8) * 16 + (h >> 1)];
            v = r ? (1.0f - k) : k;
        }
        ob[idx] = v;
    }
}

// ---------------------------------------------------------------------------
extern "C" void kernel_launch(void* const* d_in, const int* in_sizes, int n_in,
                              void* d_out, int out_size) {
    const float* x       = (const float*)d_in[0];   // (16384,4096)
    const float* latency = (const float*)d_in[1];   // (16384,)
    const float* W       = (const float*)d_in[2];   // (4096,1536)
    const float* bias    = (const float*)d_in[3];   // (1536,)
    const float* u       = (const float*)d_in[4];   // (16384,24,32,2)
    float* out = (float*)d_out;

    prep_dw_kernel<<<(HID * NCOLS + 255) / 256, 256>>>(W);
    gemm_score_kernel<<<(NB / BM) * (NCOLS / BN), 256>>>(x, bias, u);
    rank_out_kernel<<<NB, NGROUPS>>>(latency, out);
}